// round 10
// baseline (speedup 1.0000x reference)
#include <cuda_runtime.h>

// Dis_model_60129542275: bilinear flow-warp resample.
// source [16,768,1024,4] f32, flow [16,768,1024,2] f32 (dy,dx), out [16,768,1024,4] f32.
//
// R9: R6 structure (lane-pair cooperative column gathers: even lane = LEFT,
// odd = RIGHT column of both pair pixels; broadcast float4 flow per pair;
// 2 px/thread; 4 result shfls per pixel) with two fixes:
//  (a) __launch_bounds__(256, 4) -> 64-reg budget so the 8 .cg gathers are
//      genuinely register-resident and in flight (R6/R7 ran at 32-35 regs and
//      ptxas serialized the burst — the real reason MLP never materialized).
//  (b) OOB pixels (mask=0, ~8% at borders) get their tap offsets redirected to
//      element 0: all OOB lanes share one hot line instead of generating ~2.25
//      wasted wavefronts/pixel on the L1TEX binding pipe. Weights are 0, so
//      the contribution is exactly 0 either way (reference semantics).

static constexpr int Bn = 16;
static constexpr int Hn = 768;
static constexpr int Wn = 1024;
static constexpr int HW = Hn * Wn;
static constexpr int NPIX = Bn * HW;
static constexpr int THREADS = 256;
static constexpr int PIX_PER_BLOCK = 2 * THREADS;   // 512

__device__ __forceinline__ float4 ldg_cg4(const float4* p) {
    float4 v;
    asm("ld.global.cg.v4.f32 {%0,%1,%2,%3}, [%4];"
        : "=f"(v.x), "=f"(v.y), "=f"(v.z), "=f"(v.w)
        : "l"(p));
    return v;
}

struct Meta { int off0, off1; float g0, g1; };

// Per-pixel, per-column metadata: offsets of (y0,xsel) and (y1,xsel) and the
// matching bilinear weights (mask folded in). xsel = x0 for even lanes, x1 for
// odd lanes. In-bounds pixels get clamp-identical exact taps; OOB pixels get
// offset 0 (weights are 0, value irrelevant, and the shared line is cheap).
__device__ __forceinline__ Meta setup_px(int p, float dy, float dx, bool even)
{
    const int x = p & (Wn - 1);                    // Wn = 2^10
    const int r = p >> 10;
    const int b = (int)((unsigned)r / (unsigned)Hn);
    const int y = r - b * Hn;

    const float wy = (float)y + dy;
    const float wx = (float)x + dx;

    const bool inb = (wy >= 0.0f) & (wy <= (float)(Hn - 1)) &
                     (wx >= 0.0f) & (wx <= (float)(Wn - 1));
    const float m = inb ? 1.0f : 0.0f;

    const float fy = floorf(wy);
    const float fx = floorf(wx);
    const float wrt = wx - fx;                     // right weight
    const float wdn = wy - fy;                     // down weight
    const float wcol = even ? (1.0f - wrt) : wrt;  // this lane's column weight
    const float wup = (1.0f - wdn) * m;
    const float wdm = wdn * m;

    const int x0 = min(max((int)fx, 0), Wn - 1);
    const int y0 = min(max((int)fy, 0), Hn - 1);
    const int xs = even ? x0 : min(x0 + 1, Wn - 1);
    const int y1 = min(y0 + 1, Hn - 1);

    Meta mt;
    const int base = b * HW + xs;
    // OOB -> element 0: one shared, cache-hot line for all masked lanes.
    mt.off0 = inb ? (base + y0 * Wn) : 0;
    mt.off1 = inb ? (base + y1 * Wn) : 0;
    mt.g0 = wcol * wup;
    mt.g1 = wcol * wdm;
    return mt;
}

__global__ __launch_bounds__(THREADS, 4) void warp_bilinear_r9_kernel(
    const float4* __restrict__ src,    // [B*H*W] float4 (C=4)
    const float4* __restrict__ flow4,  // [B*H*W/2] float4 = 2 pixels' (dy,dx)
    float4* __restrict__ out)          // [B*H*W] float4
{
    const int tid = threadIdx.x;
    const bool even = ((tid & 1) == 0);
    const unsigned FULL = 0xffffffffu;
    const int p0 = blockIdx.x * PIX_PER_BLOCK + tid;

    Meta mA[2], mB[2];

    #pragma unroll
    for (int j = 0; j < 2; ++j) {
        const int p = p0 + j * THREADS;
        const int pA = p & ~1;                       // even pixel of the pair
        // One float4 = (dyA, dxA, dyB, dxB); broadcast across the lane pair.
        const float4 f = __ldg(flow4 + (pA >> 1));
        mA[j] = setup_px(pA,     f.x, f.y, even);    // pixel A (even lane's own)
        mB[j] = setup_px(pA | 1, f.z, f.w, even);    // pixel B (odd lane's own)
    }

    // 8 gathers issued back-to-back; with the 64-reg budget all 8 results are
    // register-resident, so the burst truly overlaps. Pair lanes' addresses
    // are 16B apart -> one 128B wavefront with p=7/8.
    float4 TA0[2], TA1[2], TB0[2], TB1[2];
    #pragma unroll
    for (int j = 0; j < 2; ++j) {
        TA0[j] = ldg_cg4(src + mA[j].off0);
        TA1[j] = ldg_cg4(src + mA[j].off1);
        TB0[j] = ldg_cg4(src + mB[j].off0);
        TB1[j] = ldg_cg4(src + mB[j].off1);
    }

    #pragma unroll
    for (int j = 0; j < 2; ++j) {
        // This lane's column partial for each pair pixel.
        float4 pAc, pBc;
        pAc.x = TA0[j].x * mA[j].g0 + TA1[j].x * mA[j].g1;
        pAc.y = TA0[j].y * mA[j].g0 + TA1[j].y * mA[j].g1;
        pAc.z = TA0[j].z * mA[j].g0 + TA1[j].z * mA[j].g1;
        pAc.w = TA0[j].w * mA[j].g0 + TA1[j].w * mA[j].g1;
        pBc.x = TB0[j].x * mB[j].g0 + TB1[j].x * mB[j].g1;
        pBc.y = TB0[j].y * mB[j].g0 + TB1[j].y * mB[j].g1;
        pBc.z = TB0[j].z * mB[j].g0 + TB1[j].z * mB[j].g1;
        pBc.w = TB0[j].w * mB[j].g0 + TB1[j].w * mB[j].g1;

        // Exchange the partner pixel's partial; keep own pixel's.
        float4 sendv;
        sendv.x = even ? pBc.x : pAc.x;
        sendv.y = even ? pBc.y : pAc.y;
        sendv.z = even ? pBc.z : pAc.z;
        sendv.w = even ? pBc.w : pAc.w;

        float4 res;
        res.x = (even ? pAc.x : pBc.x) + __shfl_xor_sync(FULL, sendv.x, 1);
        res.y = (even ? pAc.y : pBc.y) + __shfl_xor_sync(FULL, sendv.y, 1);
        res.z = (even ? pAc.z : pBc.z) + __shfl_xor_sync(FULL, sendv.z, 1);
        res.w = (even ? pAc.w : pBc.w) + __shfl_xor_sync(FULL, sendv.w, 1);

        out[p0 + j * THREADS] = res;   // own pixel (even lane = pixel A)
    }
}

extern "C" void kernel_launch(void* const* d_in, const int* in_sizes, int n_in,
                              void* d_out, int out_size)
{
    const float4* src   = (const float4*)d_in[0];   // source [16,768,1024,4]
    const float4* flow4 = (const float4*)d_in[1];   // flow   [16,768,1024,2] as float4 pairs
    float4* out = (float4*)d_out;

    static_assert(NPIX % PIX_PER_BLOCK == 0, "exact grid");
    constexpr int blocks = NPIX / PIX_PER_BLOCK;    // 24576
    warp_bilinear_r9_kernel<<<blocks, THREADS>>>(src, flow4, out);
}